// round 1
// baseline (speedup 1.0000x reference)
#include <cuda_runtime.h>

// ---------------------------------------------------------------------------
// GASP_EGNN coordinate update on GB300 (sm_103a)
// out = coord + segment_sum( (coord[r]-coord[c])/(||.||+1) * MLP(h[r],h[c],ea) , r) / 100
//
// Strategy: persistent CTAs, weights in smem, warp processes 8 edges at once
// with all math in packed f32x2 FMA (fma.rn.f32x2) to double FMA-pipe tput.
// ---------------------------------------------------------------------------

#define HID 64
#define EIN 8
#define DIN (2*HID + EIN)   // 136
#define EPW 8               // edges per warp-group (4 packed pairs)

typedef unsigned long long ull;

__device__ __forceinline__ ull pack2(float a, float b) {
    ull r; asm("mov.b64 %0, {%1,%2};" : "=l"(r) : "f"(a), "f"(b)); return r;
}
__device__ __forceinline__ void unpack2(ull p, float& a, float& b) {
    asm("mov.b64 {%0,%1}, %2;" : "=f"(a), "=f"(b) : "l"(p));
}
__device__ __forceinline__ ull fma2(ull a, ull b, ull c) {
    ull d; asm("fma.rn.f32x2 %0, %1, %2, %3;" : "=l"(d) : "l"(a), "l"(b), "l"(c)); return d;
}
__device__ __forceinline__ ull add2(ull a, ull b) {
    ull d; asm("add.rn.f32x2 %0, %1, %2;" : "=l"(d) : "l"(a), "l"(b)); return d;
}
__device__ __forceinline__ ull mul2(ull a, ull b) {
    ull d; asm("mul.rn.f32x2 %0, %1, %2;" : "=l"(d) : "l"(a), "l"(b)); return d;
}
__device__ __forceinline__ float silu1(float x) {
    return x / (1.0f + __expf(-x));
}
__device__ __forceinline__ ull silu2(ull p) {
    float a, b; unpack2(p, a, b);
    return pack2(silu1(a), silu1(b));
}

__global__ void egnn_init_out(const float* __restrict__ coord, float* __restrict__ out, int n) {
    int i = blockIdx.x * blockDim.x + threadIdx.x;
    if (i < n) out[i] = coord[i];
}

// smem layout (floats):
//   sW1[DIN*HID]  sW2[HID*HID]  sB1[HID]  sB2[HID]  sW3[HID]
//   per-warp stage: sInp[DIN*EPW]  sX1[HID*EPW]
#define SMEM_FLOATS (DIN*HID + HID*HID + 3*HID + 8*(DIN*EPW + HID*EPW))
#define SMEM_BYTES  (SMEM_FLOATS * 4)

__global__ __launch_bounds__(256, 2)
void egnn_edge_kernel(
    const float* __restrict__ h, const float* __restrict__ coord,
    const int*   __restrict__ ei, const float* __restrict__ ea,
    const float* __restrict__ W1, const float* __restrict__ b1,
    const float* __restrict__ W2, const float* __restrict__ b2,
    const float* __restrict__ W3, float* __restrict__ out, int E)
{
    extern __shared__ float sm[];
    float* sW1 = sm;
    float* sW2 = sW1 + DIN * HID;
    float* sB1 = sW2 + HID * HID;
    float* sB2 = sB1 + HID;
    float* sW3 = sB2 + HID;
    float* sStage = sW3 + HID;

    const int tid  = threadIdx.x;
    const int lane = tid & 31;
    const int wid  = tid >> 5;
    float* sInp = sStage + wid * (DIN * EPW + HID * EPW);
    float* sX1  = sInp + DIN * EPW;

    // cooperative weight staging (once per CTA, persistent grid amortizes it)
    for (int i = tid; i < DIN * HID; i += blockDim.x) sW1[i] = W1[i];
    for (int i = tid; i < HID * HID; i += blockDim.x) sW2[i] = W2[i];
    if (tid < HID) { sB1[tid] = b1[tid]; sB2[tid] = b2[tid]; sW3[tid] = W3[tid]; }
    __syncthreads();

    const int c0 = 2 * lane, c1 = c0 + 1;
    const ull bias1_0 = pack2(sB1[c0], sB1[c0]);
    const ull bias1_1 = pack2(sB1[c1], sB1[c1]);
    const ull bias2_0 = pack2(sB2[c0], sB2[c0]);
    const ull bias2_1 = pack2(sB2[c1], sB2[c1]);
    const ull w3p0 = pack2(sW3[c0], sW3[c0]);
    const ull w3p1 = pack2(sW3[c1], sW3[c1]);

    const int nwarps  = gridDim.x * (blockDim.x >> 5);
    const int gwid    = blockIdx.x * (blockDim.x >> 5) + wid;
    const int ngroups = E / EPW;          // E divisible by 8 (1.6M)
    const unsigned FULL = 0xffffffffu;

    const float2* W1v = (const float2*)sW1;
    const float2* W2v = (const float2*)sW2;

    for (int g = gwid; g < ngroups; g += nwarps) {
        const int ebase = g * EPW;

        // lanes 0..7 hold row idx, 8..15 hold col idx
        int t = 0;
        if (lane < 8)       t = ei[ebase + lane];
        else if (lane < 16) t = ei[E + ebase + lane - 8];

        // ---- stage inputs: sInp[feat*8 + e] ----
        #pragma unroll
        for (int e = 0; e < EPW; e++) {
            int rn = __shfl_sync(FULL, t, e);
            int cn = __shfl_sync(FULL, t, 8 + e);
            #pragma unroll
            for (int rd = 0; rd < 2; rd++) {
                int i = rd * 32 + lane;
                sInp[i * EPW + e]         = h[rn * HID + i];
                sInp[(HID + i) * EPW + e] = h[cn * HID + i];
            }
        }
        #pragma unroll
        for (int rd = 0; rd < 2; rd++) {
            int idx = rd * 32 + lane;
            int e = idx >> 3, i = idx & 7;
            sInp[(2 * HID + i) * EPW + e] = ea[(ebase + e) * EIN + i];
        }
        __syncwarp();

        // ---- layer 1: [8, 136] x [136, 64] ----
        ull a0[4], a1[4];
        #pragma unroll
        for (int p = 0; p < 4; p++) { a0[p] = bias1_0; a1[p] = bias1_1; }

        #pragma unroll 4
        for (int i = 0; i < DIN; i++) {
            float2 wv = W1v[i * 32 + lane];
            ull w0 = pack2(wv.x, wv.x);
            ull w1 = pack2(wv.y, wv.y);
            const ull* ip = (const ull*)(sInp + i * EPW);
            #pragma unroll
            for (int p = 0; p < 4; p++) {
                ull x = ip[p];
                a0[p] = fma2(x, w0, a0[p]);
                a1[p] = fma2(x, w1, a1[p]);
            }
        }

        // silu -> stage x1: sX1[col*8 + pair*2 + {0,1}]
        float2* x1v = (float2*)sX1;
        #pragma unroll
        for (int p = 0; p < 4; p++) {
            ull s0 = silu2(a0[p]), s1 = silu2(a1[p]);
            float2 f0, f1;
            unpack2(s0, f0.x, f0.y);
            unpack2(s1, f1.x, f1.y);
            x1v[c0 * 4 + p] = f0;
            x1v[c1 * 4 + p] = f1;
        }
        __syncwarp();

        // ---- layer 2: [8, 64] x [64, 64] ----
        ull d0[4], d1[4];
        #pragma unroll
        for (int p = 0; p < 4; p++) { d0[p] = bias2_0; d1[p] = bias2_1; }

        #pragma unroll 4
        for (int i = 0; i < HID; i++) {
            float2 wv = W2v[i * 32 + lane];
            ull w0 = pack2(wv.x, wv.x);
            ull w1 = pack2(wv.y, wv.y);
            const ull* ip = (const ull*)(sX1 + i * EPW);
            #pragma unroll
            for (int p = 0; p < 4; p++) {
                ull x = ip[p];
                d0[p] = fma2(x, w0, d0[p]);
                d1[p] = fma2(x, w1, d1[p]);
            }
        }

        // ---- layer 3: silu(x2) . W3 , warp-reduce over the 64 cols ----
        ull pp[4];
        #pragma unroll
        for (int p = 0; p < 4; p++) {
            ull x20 = silu2(d0[p]);
            ull x21 = silu2(d1[p]);
            pp[p] = fma2(x21, w3p1, mul2(x20, w3p0));
        }
        #pragma unroll
        for (int off = 16; off > 0; off >>= 1) {
            #pragma unroll
            for (int p = 0; p < 4; p++)
                pp[p] = add2(pp[p], __shfl_xor_sync(FULL, pp[p], off));
        }

        // ---- epilogue: 4 lanes per edge (k=0..2 active) ----
        const int e = lane >> 2;       // 0..7
        const int k = lane & 3;        // 0..3 (3 idle)
        const int q = e >> 1;
        ull ppe = (q == 0) ? pp[0] : (q == 1) ? pp[1] : (q == 2) ? pp[2] : pp[3];
        float slo, shi; unpack2(ppe, slo, shi);
        const float sc = (e & 1) ? shi : slo;

        const int rn = __shfl_sync(FULL, t, e);
        const int cn = __shfl_sync(FULL, t, 8 + e);
        float cd = 0.0f;
        if (k < 3) cd = coord[rn * 3 + k] - coord[cn * 3 + k];
        float sq = cd * cd;
        sq += __shfl_xor_sync(FULL, sq, 1);
        sq += __shfl_xor_sync(FULL, sq, 2);
        const float norm = sqrtf(sq + 1e-8f);
        const float f = sc / ((norm + 1.0f) * 100.0f);
        if (k < 3) atomicAdd(&out[rn * 3 + k], cd * f);
        __syncwarp();
    }
}

extern "C" void kernel_launch(void* const* d_in, const int* in_sizes, int n_in,
                              void* d_out, int out_size)
{
    const float* h     = (const float*)d_in[0];
    const float* coord = (const float*)d_in[1];
    const int*   ei    = (const int*)  d_in[2];
    const float* ea    = (const float*)d_in[3];
    const float* W1    = (const float*)d_in[4];
    const float* b1    = (const float*)d_in[5];
    const float* W2    = (const float*)d_in[6];
    const float* b2    = (const float*)d_in[7];
    const float* W3    = (const float*)d_in[8];
    float* out = (float*)d_out;

    const int E = in_sizes[3] / EIN;   // 1,600,000

    egnn_init_out<<<(out_size + 255) / 256, 256>>>(coord, out, out_size);

    cudaFuncSetAttribute(egnn_edge_kernel,
                         cudaFuncAttributeMaxDynamicSharedMemorySize, SMEM_BYTES);
    egnn_edge_kernel<<<296, 256, SMEM_BYTES>>>(h, coord, ei, ea,
                                               W1, b1, W2, b2, W3, out, E);
}

// round 2
// speedup vs baseline: 1.2247x; 1.2247x over previous
#include <cuda_runtime.h>

// ---------------------------------------------------------------------------
// GASP_EGNN coordinate update on GB300 (sm_103a) — round 2
// out = coord + segment_sum( (coord[r]-coord[c])/(||.||+1) * MLP(h[r],h[c],ea), r) / 100
//
// R2: 16 edges x 64 cols per warp, 3 LDS.128 per k-step (was 5 LDS.64 per 8
// edges), K-chunked input staging, all math packed f32x2 FMA.
// ---------------------------------------------------------------------------

#define HID 64
#define EIN 8
#define DIN (2*HID + EIN)   // 136
#define EPW 16              // edges per warp
#define PAD 20              // float stride per feature row in stage buffer
#define BUF_FLOATS (HID*PAD)   // 1280 floats = 5120 B per warp

typedef unsigned long long ull;

__device__ __forceinline__ ull pack2(float a, float b) {
    ull r; asm("mov.b64 %0, {%1,%2};" : "=l"(r) : "f"(a), "f"(b)); return r;
}
__device__ __forceinline__ void unpack2(ull p, float& a, float& b) {
    asm("mov.b64 {%0,%1}, %2;" : "=f"(a), "=f"(b) : "l"(p));
}
__device__ __forceinline__ ull fma2(ull a, ull b, ull c) {
    ull d; asm("fma.rn.f32x2 %0, %1, %2, %3;" : "=l"(d) : "l"(a), "l"(b), "l"(c)); return d;
}
__device__ __forceinline__ ull mul2(ull a, ull b) {
    ull d; asm("mul.rn.f32x2 %0, %1, %2;" : "=l"(d) : "l"(a), "l"(b)); return d;
}
__device__ __forceinline__ ull add2(ull a, ull b) {
    ull d; asm("add.rn.f32x2 %0, %1, %2;" : "=l"(d) : "l"(a), "l"(b)); return d;
}
__device__ __forceinline__ float silu1(float x) { return x / (1.0f + __expf(-x)); }
__device__ __forceinline__ ull silu2(ull p) {
    float a, b; unpack2(p, a, b);
    return pack2(silu1(a), silu1(b));
}

__global__ void egnn_init_out(const float* __restrict__ coord, float* __restrict__ out, int n) {
    int i = blockIdx.x * blockDim.x + threadIdx.x;
    if (i < n) out[i] = coord[i];
}

// smem floats: sW1[136*64]  sW2[64*64]  sB1[64] sB2[64] sW3[64]  + 8 warps * BUF
#define SMEM_FLOATS (DIN*HID + HID*HID + 3*HID + 8*BUF_FLOATS)
#define SMEM_BYTES  (SMEM_FLOATS * 4)

__global__ __launch_bounds__(256, 2)
void egnn_edge_kernel(
    const float* __restrict__ h, const float* __restrict__ coord,
    const int*   __restrict__ ei, const float* __restrict__ ea,
    const float* __restrict__ W1, const float* __restrict__ b1,
    const float* __restrict__ W2, const float* __restrict__ b2,
    const float* __restrict__ W3, float* __restrict__ out, int E)
{
    extern __shared__ float sm[];
    float* sW1 = sm;                       // [136][64]
    float* sW2 = sW1 + DIN * HID;          // [64][64]
    float* sB1 = sW2 + HID * HID;
    float* sB2 = sB1 + HID;
    float* sW3 = sB2 + HID;
    float* sBufAll = sW3 + HID;

    const int tid  = threadIdx.x;
    const int lane = tid & 31;
    const int wid  = tid >> 5;
    float* sBuf = sBufAll + wid * BUF_FLOATS;   // per-warp [64][PAD]

    // cooperative weight staging (once per persistent CTA)
    {
        const float4* W1v = (const float4*)W1;
        const float4* W2v = (const float4*)W2;
        float4* sW1v = (float4*)sW1;
        float4* sW2v = (float4*)sW2;
        for (int i = tid; i < DIN * HID / 4; i += blockDim.x) sW1v[i] = W1v[i];
        for (int i = tid; i < HID * HID / 4; i += blockDim.x) sW2v[i] = W2v[i];
        if (tid < HID) { sB1[tid] = b1[tid]; sB2[tid] = b2[tid]; sW3[tid] = W3[tid]; }
    }
    __syncthreads();

    const int cg = lane >> 1;     // 0..15 col group (4 cols each)
    const int eg = lane & 1;      // 0..1 edge group (8 edges each)
    const int c0 = 4 * cg;

    // hoisted per-col constants
    ull b1s[4], b2s[4], w3s[4];
    #pragma unroll
    for (int j = 0; j < 4; j++) {
        b1s[j] = pack2(sB1[c0 + j], sB1[c0 + j]);
        b2s[j] = pack2(sB2[c0 + j], sB2[c0 + j]);
        w3s[j] = pack2(sW3[c0 + j], sW3[c0 + j]);
    }

    const int nwarps  = gridDim.x * (blockDim.x >> 5);
    const int gwid    = blockIdx.x * (blockDim.x >> 5) + wid;
    const int ngroups = E / EPW;
    const unsigned FULL = 0xffffffffu;

    const int e_st  = lane & 15;  // staging edge
    const int part  = lane >> 4;  // staging feature half (0/1)

    for (int g = gwid; g < ngroups; g += nwarps) {
        const int ebase = g * EPW;

        // lanes 0..15: rn[lane], lanes 16..31: cn[lane-16]
        int t;
        if (lane < 16) t = ei[ebase + lane];
        else           t = ei[E + ebase + lane - 16];

        const int node_r = __shfl_sync(FULL, t, e_st);
        const int node_c = __shfl_sync(FULL, t, 16 + e_st);

        ull a[4][4];   // [col j][edge-pair p]
        #pragma unroll
        for (int j = 0; j < 4; j++)
            #pragma unroll
            for (int p = 0; p < 4; p++) a[j][p] = b1s[j];

        // ================= layer 1, chunk A: h[row], W1 rows 0..63 ==========
        {
            const float* hr = h + (size_t)node_r * HID + part * 32;
            #pragma unroll
            for (int it = 0; it < 8; it++) {
                float4 v = *(const float4*)(hr + it * 4);
                int kb = part * 32 + it * 4;
                sBuf[(kb + 0) * PAD + e_st] = v.x;
                sBuf[(kb + 1) * PAD + e_st] = v.y;
                sBuf[(kb + 2) * PAD + e_st] = v.z;
                sBuf[(kb + 3) * PAD + e_st] = v.w;
            }
        }
        __syncwarp();
        {
            const float* Wp = sW1;   // rows 0..63
            #pragma unroll 8
            for (int k = 0; k < HID; k++) {
                float4 wv = *(const float4*)(Wp + k * HID + c0);
                ull w0 = pack2(wv.x, wv.x), w1 = pack2(wv.y, wv.y);
                ull w2 = pack2(wv.z, wv.z), w3 = pack2(wv.w, wv.w);
                const ulonglong2* xp = (const ulonglong2*)(sBuf + k * PAD + eg * 8);
                ulonglong2 xa = xp[0], xb = xp[1];
                a[0][0]=fma2(xa.x,w0,a[0][0]); a[0][1]=fma2(xa.y,w0,a[0][1]);
                a[0][2]=fma2(xb.x,w0,a[0][2]); a[0][3]=fma2(xb.y,w0,a[0][3]);
                a[1][0]=fma2(xa.x,w1,a[1][0]); a[1][1]=fma2(xa.y,w1,a[1][1]);
                a[1][2]=fma2(xb.x,w1,a[1][2]); a[1][3]=fma2(xb.y,w1,a[1][3]);
                a[2][0]=fma2(xa.x,w2,a[2][0]); a[2][1]=fma2(xa.y,w2,a[2][1]);
                a[2][2]=fma2(xb.x,w2,a[2][2]); a[2][3]=fma2(xb.y,w2,a[2][3]);
                a[3][0]=fma2(xa.x,w3,a[3][0]); a[3][1]=fma2(xa.y,w3,a[3][1]);
                a[3][2]=fma2(xb.x,w3,a[3][2]); a[3][3]=fma2(xb.y,w3,a[3][3]);
            }
        }
        __syncwarp();

        // ================= layer 1, chunk B: h[col], W1 rows 64..127 ========
        {
            const float* hc = h + (size_t)node_c * HID + part * 32;
            #pragma unroll
            for (int it = 0; it < 8; it++) {
                float4 v = *(const float4*)(hc + it * 4);
                int kb = part * 32 + it * 4;
                sBuf[(kb + 0) * PAD + e_st] = v.x;
                sBuf[(kb + 1) * PAD + e_st] = v.y;
                sBuf[(kb + 2) * PAD + e_st] = v.z;
                sBuf[(kb + 3) * PAD + e_st] = v.w;
            }
        }
        __syncwarp();
        {
            const float* Wp = sW1 + 64 * HID;   // rows 64..127
            #pragma unroll 8
            for (int k = 0; k < HID; k++) {
                float4 wv = *(const float4*)(Wp + k * HID + c0);
                ull w0 = pack2(wv.x, wv.x), w1 = pack2(wv.y, wv.y);
                ull w2 = pack2(wv.z, wv.z), w3 = pack2(wv.w, wv.w);
                const ulonglong2* xp = (const ulonglong2*)(sBuf + k * PAD + eg * 8);
                ulonglong2 xa = xp[0], xb = xp[1];
                a[0][0]=fma2(xa.x,w0,a[0][0]); a[0][1]=fma2(xa.y,w0,a[0][1]);
                a[0][2]=fma2(xb.x,w0,a[0][2]); a[0][3]=fma2(xb.y,w0,a[0][3]);
                a[1][0]=fma2(xa.x,w1,a[1][0]); a[1][1]=fma2(xa.y,w1,a[1][1]);
                a[1][2]=fma2(xb.x,w1,a[1][2]); a[1][3]=fma2(xb.y,w1,a[1][3]);
                a[2][0]=fma2(xa.x,w2,a[2][0]); a[2][1]=fma2(xa.y,w2,a[2][1]);
                a[2][2]=fma2(xb.x,w2,a[2][2]); a[2][3]=fma2(xb.y,w2,a[2][3]);
                a[3][0]=fma2(xa.x,w3,a[3][0]); a[3][1]=fma2(xa.y,w3,a[3][1]);
                a[3][2]=fma2(xb.x,w3,a[3][2]); a[3][3]=fma2(xb.y,w3,a[3][3]);
            }
        }
        __syncwarp();

        // ================= layer 1, chunk C: edge_attr, W1 rows 128..135 ====
        {
            const int e2 = lane >> 1, half = lane & 1;   // 16 edges x 2 halves
            float4 v = *(const float4*)(ea + (size_t)(ebase + e2) * EIN + half * 4);
            sBuf[(half * 4 + 0) * PAD + e2] = v.x;
            sBuf[(half * 4 + 1) * PAD + e2] = v.y;
            sBuf[(half * 4 + 2) * PAD + e2] = v.z;
            sBuf[(half * 4 + 3) * PAD + e2] = v.w;
        }
        __syncwarp();
        {
            const float* Wp = sW1 + 128 * HID;   // rows 128..135
            #pragma unroll
            for (int k = 0; k < EIN; k++) {
                float4 wv = *(const float4*)(Wp + k * HID + c0);
                ull w0 = pack2(wv.x, wv.x), w1 = pack2(wv.y, wv.y);
                ull w2 = pack2(wv.z, wv.z), w3 = pack2(wv.w, wv.w);
                const ulonglong2* xp = (const ulonglong2*)(sBuf + k * PAD + eg * 8);
                ulonglong2 xa = xp[0], xb = xp[1];
                a[0][0]=fma2(xa.x,w0,a[0][0]); a[0][1]=fma2(xa.y,w0,a[0][1]);
                a[0][2]=fma2(xb.x,w0,a[0][2]); a[0][3]=fma2(xb.y,w0,a[0][3]);
                a[1][0]=fma2(xa.x,w1,a[1][0]); a[1][1]=fma2(xa.y,w1,a[1][1]);
                a[1][2]=fma2(xb.x,w1,a[1][2]); a[1][3]=fma2(xb.y,w1,a[1][3]);
                a[2][0]=fma2(xa.x,w2,a[2][0]); a[2][1]=fma2(xa.y,w2,a[2][1]);
                a[2][2]=fma2(xb.x,w2,a[2][2]); a[2][3]=fma2(xb.y,w2,a[2][3]);
                a[3][0]=fma2(xa.x,w3,a[3][0]); a[3][1]=fma2(xa.y,w3,a[3][1]);
                a[3][2]=fma2(xb.x,w3,a[3][2]); a[3][3]=fma2(xb.y,w3,a[3][3]);
            }
        }
        __syncwarp();

        // ========== silu -> store x1 into sBuf[k=col][e] (reuse buffer) =====
        #pragma unroll
        for (int j = 0; j < 4; j++) {
            #pragma unroll
            for (int p = 0; p < 4; p++) {
                *(ull*)(sBuf + (c0 + j) * PAD + eg * 8 + 2 * p) = silu2(a[j][p]);
            }
        }
        __syncwarp();

        // ================= layer 2: [16,64] x [64,64] =======================
        ull d[4][4];
        #pragma unroll
        for (int j = 0; j < 4; j++)
            #pragma unroll
            for (int p = 0; p < 4; p++) d[j][p] = b2s[j];

        #pragma unroll 8
        for (int k = 0; k < HID; k++) {
            float4 wv = *(const float4*)(sW2 + k * HID + c0);
            ull w0 = pack2(wv.x, wv.x), w1 = pack2(wv.y, wv.y);
            ull w2 = pack2(wv.z, wv.z), w3 = pack2(wv.w, wv.w);
            const ulonglong2* xp = (const ulonglong2*)(sBuf + k * PAD + eg * 8);
            ulonglong2 xa = xp[0], xb = xp[1];
            d[0][0]=fma2(xa.x,w0,d[0][0]); d[0][1]=fma2(xa.y,w0,d[0][1]);
            d[0][2]=fma2(xb.x,w0,d[0][2]); d[0][3]=fma2(xb.y,w0,d[0][3]);
            d[1][0]=fma2(xa.x,w1,d[1][0]); d[1][1]=fma2(xa.y,w1,d[1][1]);
            d[1][2]=fma2(xb.x,w1,d[1][2]); d[1][3]=fma2(xb.y,w1,d[1][3]);
            d[2][0]=fma2(xa.x,w2,d[2][0]); d[2][1]=fma2(xa.y,w2,d[2][1]);
            d[2][2]=fma2(xb.x,w2,d[2][2]); d[2][3]=fma2(xb.y,w2,d[2][3]);
            d[3][0]=fma2(xa.x,w3,d[3][0]); d[3][1]=fma2(xa.y,w3,d[3][1]);
            d[3][2]=fma2(xb.x,w3,d[3][2]); d[3][3]=fma2(xb.y,w3,d[3][3]);
        }
        __syncwarp();

        // ========== layer 3: silu(x2) . W3, reduce over 16 col groups =======
        ull pp[4];
        #pragma unroll
        for (int p = 0; p < 4; p++) {
            ull s = mul2(silu2(d[0][p]), w3s[0]);
            s = fma2(silu2(d[1][p]), w3s[1], s);
            s = fma2(silu2(d[2][p]), w3s[2], s);
            s = fma2(silu2(d[3][p]), w3s[3], s);
            pp[p] = s;
        }
        #pragma unroll
        for (int off = 2; off < 32; off <<= 1) {
            #pragma unroll
            for (int p = 0; p < 4; p++)
                pp[p] = add2(pp[p], __shfl_xor_sync(FULL, pp[p], off));
        }

        // ========== epilogue: 1 lane per edge (lanes 0..15) =================
        const int e   = lane & 15;
        const int src = e >> 3;              // lane with matching edge-group
        ull q0 = __shfl_sync(FULL, pp[0], src);
        ull q1 = __shfl_sync(FULL, pp[1], src);
        ull q2 = __shfl_sync(FULL, pp[2], src);
        ull q3 = __shfl_sync(FULL, pp[3], src);
        const int pidx = (e & 7) >> 1;
        ull qq = (pidx == 0) ? q0 : (pidx == 1) ? q1 : (pidx == 2) ? q2 : q3;
        float qlo, qhi; unpack2(qq, qlo, qhi);
        const float sc = (e & 1) ? qhi : qlo;

        const int rn = __shfl_sync(FULL, t, e);
        const int cn = __shfl_sync(FULL, t, 16 + e);

        if (lane < 16) {
            const float dx = coord[rn * 3 + 0] - coord[cn * 3 + 0];
            const float dy = coord[rn * 3 + 1] - coord[cn * 3 + 1];
            const float dz = coord[rn * 3 + 2] - coord[cn * 3 + 2];
            const float sq = dx * dx + dy * dy + dz * dz;
            const float norm = sqrtf(sq + 1e-8f);
            const float f = sc / ((norm + 1.0f) * 100.0f);
            atomicAdd(&out[rn * 3 + 0], dx * f);
            atomicAdd(&out[rn * 3 + 1], dy * f);
            atomicAdd(&out[rn * 3 + 2], dz * f);
        }
        __syncwarp();
    }
}

extern "C" void kernel_launch(void* const* d_in, const int* in_sizes, int n_in,
                              void* d_out, int out_size)
{
    const float* h     = (const float*)d_in[0];
    const float* coord = (const float*)d_in[1];
    const int*   ei    = (const int*)  d_in[2];
    const float* ea    = (const float*)d_in[3];
    const float* W1    = (const float*)d_in[4];
    const float* b1    = (const float*)d_in[5];
    const float* W2    = (const float*)d_in[6];
    const float* b2    = (const float*)d_in[7];
    const float* W3    = (const float*)d_in[8];
    float* out = (float*)d_out;

    const int E = in_sizes[3] / EIN;   // 1,600,000

    egnn_init_out<<<(out_size + 255) / 256, 256>>>(coord, out, out_size);

    cudaFuncSetAttribute(egnn_edge_kernel,
                         cudaFuncAttributeMaxDynamicSharedMemorySize, SMEM_BYTES);
    egnn_edge_kernel<<<296, 256, SMEM_BYTES>>>(h, coord, ei, ea,
                                               W1, b1, W2, b2, W3, out, E);
}

// round 4
// speedup vs baseline: 1.4107x; 1.1519x over previous
#include <cuda_runtime.h>

// ---------------------------------------------------------------------------
// GASP_EGNN coordinate update on GB300 (sm_103a) — round 4 (SIMT, f32x2)
// out = coord + segment_sum( (coord[r]-coord[c])/(||.||+1) * MLP(h[r],h[c],ea), r)/100
//
// R4: tcgen05 unavailable (harness targets compute_103). SIMT path tuned:
//  - fast SiLU (MUFU.RCP + EX2, no IEEE divide)
//  - 1 CTA/SM, 512 thr, full 136-feature stage up front (batched LDG.128)
//  - single long FFMA2 loops, PAD=16 stage buffer
// ---------------------------------------------------------------------------

#define HID  64
#define EIN  8
#define DIN  (2*HID + EIN)    // 136
#define EPW  16               // edges per warp
#define PAD  16               // floats per stage row
#define ROWS 136
#define NWARPS 16
#define BUF_FLOATS (ROWS*PAD) // 2176

typedef unsigned long long ull;

__device__ __forceinline__ ull pack2(float a, float b) {
    ull r; asm("mov.b64 %0, {%1,%2};" : "=l"(r) : "f"(a), "f"(b)); return r;
}
__device__ __forceinline__ void unpack2(ull p, float& a, float& b) {
    asm("mov.b64 {%0,%1}, %2;" : "=f"(a), "=f"(b) : "l"(p));
}
__device__ __forceinline__ ull fma2(ull a, ull b, ull c) {
    ull d; asm("fma.rn.f32x2 %0, %1, %2, %3;" : "=l"(d) : "l"(a), "l"(b), "l"(c)); return d;
}
__device__ __forceinline__ ull mul2(ull a, ull b) {
    ull d; asm("mul.rn.f32x2 %0, %1, %2;" : "=l"(d) : "l"(a), "l"(b)); return d;
}
__device__ __forceinline__ ull add2(ull a, ull b) {
    ull d; asm("add.rn.f32x2 %0, %1, %2;" : "=l"(d) : "l"(a), "l"(b)); return d;
}
// fast SiLU: x * rcp(1 + exp(-x))  (MUFU.EX2 + MUFU.RCP; ~2^-21 rel err)
__device__ __forceinline__ float silu1(float x) {
    return __fdividef(x, 1.0f + __expf(-x));
}
__device__ __forceinline__ ull silu2(ull p) {
    float a, b; unpack2(p, a, b);
    return pack2(silu1(a), silu1(b));
}

__global__ void egnn_init_out(const float* __restrict__ coord, float* __restrict__ out, int n) {
    int i = blockIdx.x * blockDim.x + threadIdx.x;
    if (i < n) out[i] = coord[i];
}

// smem floats: sW1[136*64] sW2[64*64] sB1[64] sB2[64] sW3[64] + 16 warps * BUF
#define SMEM_FLOATS (DIN*HID + HID*HID + 3*HID + NWARPS*BUF_FLOATS)
#define SMEM_BYTES  (SMEM_FLOATS * 4)

// one k-step: 1 LDS.128 weights + 2 LDS.128 inputs -> 16 fma2
#define KSTEP(WROW, KIDX, ACC)                                                \
    {                                                                         \
        float4 wv = *(const float4*)((WROW) + (KIDX) * HID + c0);             \
        ull w0 = pack2(wv.x, wv.x), w1 = pack2(wv.y, wv.y);                   \
        ull w2 = pack2(wv.z, wv.z), w3 = pack2(wv.w, wv.w);                   \
        const ulonglong2* xp = (const ulonglong2*)(sBuf + (KIDX) * PAD + eg * 8); \
        ulonglong2 xa = xp[0], xb = xp[1];                                    \
        ACC[0][0]=fma2(xa.x,w0,ACC[0][0]); ACC[0][1]=fma2(xa.y,w0,ACC[0][1]); \
        ACC[0][2]=fma2(xb.x,w0,ACC[0][2]); ACC[0][3]=fma2(xb.y,w0,ACC[0][3]); \
        ACC[1][0]=fma2(xa.x,w1,ACC[1][0]); ACC[1][1]=fma2(xa.y,w1,ACC[1][1]); \
        ACC[1][2]=fma2(xb.x,w1,ACC[1][2]); ACC[1][3]=fma2(xb.y,w1,ACC[1][3]); \
        ACC[2][0]=fma2(xa.x,w2,ACC[2][0]); ACC[2][1]=fma2(xa.y,w2,ACC[2][1]); \
        ACC[2][2]=fma2(xb.x,w2,ACC[2][2]); ACC[2][3]=fma2(xb.y,w2,ACC[2][3]); \
        ACC[3][0]=fma2(xa.x,w3,ACC[3][0]); ACC[3][1]=fma2(xa.y,w3,ACC[3][1]); \
        ACC[3][2]=fma2(xb.x,w3,ACC[3][2]); ACC[3][3]=fma2(xb.y,w3,ACC[3][3]); \
    }

__global__ __launch_bounds__(512, 1)
void egnn_edge_kernel(
    const float* __restrict__ h, const float* __restrict__ coord,
    const int*   __restrict__ ei, const float* __restrict__ ea,
    const float* __restrict__ W1, const float* __restrict__ b1,
    const float* __restrict__ W2, const float* __restrict__ b2,
    const float* __restrict__ W3, float* __restrict__ out, int E)
{
    extern __shared__ float sm[];
    float* sW1 = sm;                       // [136][64]
    float* sW2 = sW1 + DIN * HID;          // [64][64]
    float* sB1 = sW2 + HID * HID;
    float* sB2 = sB1 + HID;
    float* sW3 = sB2 + HID;
    float* sBufAll = sW3 + HID;

    const int tid  = threadIdx.x;
    const int lane = tid & 31;
    const int wid  = tid >> 5;
    float* sBuf = sBufAll + wid * BUF_FLOATS;   // per-warp [136][16]

    // cooperative weight staging (once per CTA; grid=148, persistent)
    {
        const float4* W1v = (const float4*)W1;
        const float4* W2v = (const float4*)W2;
        float4* sW1v = (float4*)sW1;
        float4* sW2v = (float4*)sW2;
        for (int i = tid; i < DIN * HID / 4; i += blockDim.x) sW1v[i] = W1v[i];
        for (int i = tid; i < HID * HID / 4; i += blockDim.x) sW2v[i] = W2v[i];
        if (tid < HID) { sB1[tid] = b1[tid]; sB2[tid] = b2[tid]; sW3[tid] = W3[tid]; }
    }
    __syncthreads();

    const int cg = lane >> 1;     // 0..15 col group (4 cols)
    const int eg = lane & 1;      // edge half (8 edges)
    const int c0 = 4 * cg;

    ull b1s[4], b2s[4], w3s[4];
    #pragma unroll
    for (int j = 0; j < 4; j++) {
        b1s[j] = pack2(sB1[c0 + j], sB1[c0 + j]);
        b2s[j] = pack2(sB2[c0 + j], sB2[c0 + j]);
        w3s[j] = pack2(sW3[c0 + j], sW3[c0 + j]);
    }

    const int nwarps  = gridDim.x * NWARPS;
    const int gwid    = blockIdx.x * NWARPS + wid;
    const int ngroups = E / EPW;
    const unsigned FULL = 0xffffffffu;

    const int e_st = lane & 15;   // staging edge
    const int part = lane >> 4;   // staging feature half

    for (int g = gwid; g < ngroups; g += nwarps) {
        const int ebase = g * EPW;

        // lanes 0..15: rn, lanes 16..31: cn
        int t;
        if (lane < 16) t = ei[ebase + lane];
        else           t = ei[E + ebase + lane - 16];

        const int node_r = __shfl_sync(FULL, t, e_st);
        const int node_c = __shfl_sync(FULL, t, 16 + e_st);

        // ======== stage ALL inputs up front (batched LDGs, MLP ~17) ========
        {
            const float4* hr = (const float4*)(h + (size_t)node_r * HID + part * 32);
            const float4* hc = (const float4*)(h + (size_t)node_c * HID + part * 32);
            const int e2 = lane >> 1, half = lane & 1;
            const float4* ep = (const float4*)(ea + (size_t)(ebase + e2) * EIN + half * 4);

            float4 va[4], vb[4], vc[4], vd[4], ve;
            #pragma unroll
            for (int i = 0; i < 4; i++) va[i] = hr[i];
            #pragma unroll
            for (int i = 0; i < 4; i++) vb[i] = hr[4 + i];
            #pragma unroll
            for (int i = 0; i < 4; i++) vc[i] = hc[i];
            #pragma unroll
            for (int i = 0; i < 4; i++) vd[i] = hc[4 + i];
            ve = ep[0];

            #pragma unroll
            for (int i = 0; i < 4; i++) {
                int kb = part * 32 + i * 4;
                sBuf[(kb+0)*PAD + e_st] = va[i].x; sBuf[(kb+1)*PAD + e_st] = va[i].y;
                sBuf[(kb+2)*PAD + e_st] = va[i].z; sBuf[(kb+3)*PAD + e_st] = va[i].w;
            }
            #pragma unroll
            for (int i = 0; i < 4; i++) {
                int kb = part * 32 + 16 + i * 4;
                sBuf[(kb+0)*PAD + e_st] = vb[i].x; sBuf[(kb+1)*PAD + e_st] = vb[i].y;
                sBuf[(kb+2)*PAD + e_st] = vb[i].z; sBuf[(kb+3)*PAD + e_st] = vb[i].w;
            }
            #pragma unroll
            for (int i = 0; i < 4; i++) {
                int kb = HID + part * 32 + i * 4;
                sBuf[(kb+0)*PAD + e_st] = vc[i].x; sBuf[(kb+1)*PAD + e_st] = vc[i].y;
                sBuf[(kb+2)*PAD + e_st] = vc[i].z; sBuf[(kb+3)*PAD + e_st] = vc[i].w;
            }
            #pragma unroll
            for (int i = 0; i < 4; i++) {
                int kb = HID + part * 32 + 16 + i * 4;
                sBuf[(kb+0)*PAD + e_st] = vd[i].x; sBuf[(kb+1)*PAD + e_st] = vd[i].y;
                sBuf[(kb+2)*PAD + e_st] = vd[i].z; sBuf[(kb+3)*PAD + e_st] = vd[i].w;
            }
            {
                int kb = 2 * HID + half * 4;
                sBuf[(kb+0)*PAD + e2] = ve.x; sBuf[(kb+1)*PAD + e2] = ve.y;
                sBuf[(kb+2)*PAD + e2] = ve.z; sBuf[(kb+3)*PAD + e2] = ve.w;
            }
        }
        __syncwarp();

        // ================= layer 1: [16,136] x [136,64] =====================
        ull a[4][4];
        #pragma unroll
        for (int j = 0; j < 4; j++)
            #pragma unroll
            for (int p = 0; p < 4; p++) a[j][p] = b1s[j];

        #pragma unroll 8
        for (int k = 0; k < DIN; k++) KSTEP(sW1, k, a)
        __syncwarp();

        // ======== silu -> x1 back into sBuf rows 0..63 ======================
        #pragma unroll
        for (int j = 0; j < 4; j++)
            #pragma unroll
            for (int p = 0; p < 4; p++)
                *(ull*)(sBuf + (c0 + j) * PAD + eg * 8 + 2 * p) = silu2(a[j][p]);
        __syncwarp();

        // ================= layer 2: [16,64] x [64,64] =======================
        ull d[4][4];
        #pragma unroll
        for (int j = 0; j < 4; j++)
            #pragma unroll
            for (int p = 0; p < 4; p++) d[j][p] = b2s[j];

        #pragma unroll 8
        for (int k = 0; k < HID; k++) KSTEP(sW2, k, d)

        // ======== layer 3: silu(x2).W3, reduce across 16 col groups =========
        ull pp[4];
        #pragma unroll
        for (int p = 0; p < 4; p++) {
            ull s = mul2(silu2(d[0][p]), w3s[0]);
            s = fma2(silu2(d[1][p]), w3s[1], s);
            s = fma2(silu2(d[2][p]), w3s[2], s);
            s = fma2(silu2(d[3][p]), w3s[3], s);
            pp[p] = s;
        }
        #pragma unroll
        for (int off = 2; off < 32; off <<= 1) {
            #pragma unroll
            for (int p = 0; p < 4; p++)
                pp[p] = add2(pp[p], __shfl_xor_sync(FULL, pp[p], off));
        }

        // ======== epilogue: 1 lane per edge (lanes 0..15) ===================
        const int e   = lane & 15;
        const int src = e >> 3;
        ull q0 = __shfl_sync(FULL, pp[0], src);
        ull q1 = __shfl_sync(FULL, pp[1], src);
        ull q2 = __shfl_sync(FULL, pp[2], src);
        ull q3 = __shfl_sync(FULL, pp[3], src);
        const int pidx = (e & 7) >> 1;
        ull qq = (pidx == 0) ? q0 : (pidx == 1) ? q1 : (pidx == 2) ? q2 : q3;
        float qlo, qhi; unpack2(qq, qlo, qhi);
        const float sc = (e & 1) ? qhi : qlo;

        const int rn = __shfl_sync(FULL, t, e);
        const int cn = __shfl_sync(FULL, t, 16 + e);

        if (lane < 16) {
            const float dx = coord[rn * 3 + 0] - coord[cn * 3 + 0];
            const float dy = coord[rn * 3 + 1] - coord[cn * 3 + 1];
            const float dz = coord[rn * 3 + 2] - coord[cn * 3 + 2];
            const float sq = dx * dx + dy * dy + dz * dz;
            const float norm = sqrtf(sq + 1e-8f);
            const float f = sc / ((norm + 1.0f) * 100.0f);
            atomicAdd(&out[rn * 3 + 0], dx * f);
            atomicAdd(&out[rn * 3 + 1], dy * f);
            atomicAdd(&out[rn * 3 + 2], dz * f);
        }
        __syncwarp();
    }
}

extern "C" void kernel_launch(void* const* d_in, const int* in_sizes, int n_in,
                              void* d_out, int out_size)
{
    const float* h     = (const float*)d_in[0];
    const float* coord = (const float*)d_in[1];
    const int*   ei    = (const int*)  d_in[2];
    const float* ea    = (const float*)d_in[3];
    const float* W1    = (const float*)d_in[4];
    const float* b1    = (const float*)d_in[5];
    const float* W2    = (const float*)d_in[6];
    const float* b2    = (const float*)d_in[7];
    const float* W3    = (const float*)d_in[8];
    float* out = (float*)d_out;

    const int E = in_sizes[3] / EIN;   // 1,600,000

    egnn_init_out<<<(out_size + 255) / 256, 256>>>(coord, out, out_size);

    cudaFuncSetAttribute(egnn_edge_kernel,
                         cudaFuncAttributeMaxDynamicSharedMemorySize, SMEM_BYTES);
    egnn_edge_kernel<<<148, 512, SMEM_BYTES>>>(h, coord, ei, ea,
                                               W1, b1, W2, b2, W3, out, E);
}